// round 8
// baseline (speedup 1.0000x reference)
#include <cuda_runtime.h>

#define BATCH 4
#define H 1024
#define W 1024
#define IMG (H * W)
#define NPIX (BATCH * IMG)
#define NTILES (BATCH * 32 * 32)
#define MAXROOTS 512

// ---------------- scratch ----------------
__device__ unsigned short g_pack[NPIX];   // bits[14:16)=state, bits[0:10)=local root idx
__device__ unsigned int   g_parent[NPIX]; // valid ONLY at local-root positions
__device__ unsigned char  g_flag[NPIX];   // valid ONLY at root positions
__device__ unsigned short g_roots[NTILES * MAXROOTS];
__device__ unsigned int   g_cnt[NTILES];

__constant__ int c_dy[8] = { 0, 1, 1, 1, 0, -1, -1, -1 };
__constant__ int c_dx[8] = { 1, 1, 0, -1, -1, -1, 0, 1 };

#define GW0 0.40261994f
#define GW1 0.24420134f
#define GW2 0.05448868f
#define TAN22 0.41421356237309503f
#define TAN67 2.4142135623730951f

__device__ __forceinline__ int reflect_idx(int i, int n) {
    if (i < 0) return -i;
    if (i >= n) return 2 * n - 2 - i;
    return i;
}

// ---- shared-memory union-find ----
__device__ __forceinline__ unsigned lfind(unsigned* p, unsigned i) {
    volatile unsigned* vp = (volatile unsigned*)p;
    unsigned q = vp[i];
    while (q != i) {
        unsigned qq = vp[q];
        if (qq != q) vp[i] = qq;
        i = q; q = qq;
    }
    return i;
}
__device__ __forceinline__ void lunion(unsigned* p, unsigned a, unsigned b) {
    while (true) {
        a = lfind(p, a);
        b = lfind(p, b);
        if (a == b) return;
        unsigned lo = min(a, b), hi = max(a, b);
        unsigned old = atomicCAS(&p[hi], hi, lo);
        if (old == hi) return;
        a = lo; b = old;
    }
}

// ---- global union-find (root positions only) ----
__device__ __forceinline__ unsigned gfind(unsigned i) {
    unsigned p = __ldcg(&g_parent[i]);
    while (p != i) {
        unsigned gp = __ldcg(&g_parent[p]);
        if (gp != p) __stcg(&g_parent[i], gp);
        i = p; p = gp;
    }
    return i;
}
__device__ __forceinline__ void gunion(unsigned a, unsigned b) {
    while (true) {
        a = gfind(a);
        b = gfind(b);
        if (a == b) return;
        unsigned lo = min(a, b), hi = max(a, b);
        unsigned old = atomicCAS(&g_parent[hi], hi, lo);
        if (old == hi) return;
        a = lo; b = old;
    }
}

// decode a pixel's local-root global position from its packed value
__device__ __forceinline__ unsigned rootPos(unsigned j, unsigned pk) {
    unsigned l = pk & 1023u;
    unsigned b = j >> 20;
    unsigned y = (j >> 10) & 1023u;
    unsigned x = j & 1023u;
    return (b << 20) + (((y & ~31u) + (l >> 5)) << 10) + (x & ~31u) + (l & 31u);
}

// ================= fused stencil + NMS + threshold + local CCL =================
#define TX 32
#define TY 32

__global__ __launch_bounds__(1024) void k_fused(const float* __restrict__ x,
                                                float* __restrict__ magOut) {
    __shared__ float sG[40][41];
    __shared__ float sH[40][37];
    __shared__ float sV[36][37];
    __shared__ float sM[34][35];
    __shared__ unsigned char sD[34][35];
    __shared__ unsigned      lp[1024];
    __shared__ unsigned char ls[1024];
    __shared__ unsigned char sflag[1024];
    __shared__ unsigned scnt;

    const int tileX = blockIdx.x * TX;
    const int tileY = blockIdx.y * TY;
    const int b     = blockIdx.z;
    const int tid   = threadIdx.y * TX + threadIdx.x;
    const unsigned tileId = ((unsigned)b * 32 + blockIdx.y) * 32 + blockIdx.x;
    const float* base = x + (size_t)b * 3 * IMG;

    if (tid == 0) scnt = 0;

    for (int idx = tid; idx < 40 * 40; idx += 1024) {
        int r = idx / 40, c = idx % 40;
        int yy = reflect_idx(tileY - 4 + r, H);
        int xx = reflect_idx(tileX - 4 + c, W);
        int o = yy * W + xx;
        sG[r][c] = 0.299f * base[o] + 0.587f * base[IMG + o] + 0.114f * base[2 * IMG + o];
    }
    __syncthreads();

    for (int idx = tid; idx < 40 * 36; idx += 1024) {
        int r = idx / 36, c = idx % 36;
        int gx = tileX - 2 + c;
        float s = 0.f;
        const float w[5] = { GW2, GW1, GW0, GW1, GW2 };
#pragma unroll
        for (int k = 0; k < 5; k++) {
            int lx = reflect_idx(gx + k - 2, W) - (tileX - 4);
            s += w[k] * sG[r][lx];
        }
        sH[r][c] = s;
    }
    __syncthreads();

    for (int idx = tid; idx < 36 * 36; idx += 1024) {
        int r = idx / 36, c = idx % 36;
        int gy = tileY - 2 + r;
        float s = 0.f;
        const float w[5] = { GW2, GW1, GW0, GW1, GW2 };
#pragma unroll
        for (int k = 0; k < 5; k++) {
            int ly = reflect_idx(gy + k - 2, H) - (tileY - 4);
            s += w[k] * sH[ly][c];
        }
        sV[r][c] = s;
    }
    __syncthreads();

    for (int idx = tid; idx < 34 * 34; idx += 1024) {
        int r = idx / 34, c = idx % 34;
        int gy = tileY - 1 + r;
        int gx = tileX - 1 + c;
        int xm = max(gx - 1, 0), xp = min(gx + 1, W - 1);
        int ym = max(gy - 1, 0), yp = min(gy + 1, H - 1);
        int xc = min(max(gx, 0), W - 1), yc = min(max(gy, 0), H - 1);
        int lxm = xm - (tileX - 2), lxp = xp - (tileX - 2), lxc = xc - (tileX - 2);
        int lym = ym - (tileY - 2), lyp = yp - (tileY - 2), lyc = yc - (tileY - 2);

        float a00 = sV[lym][lxm], a01 = sV[lym][lxc], a02 = sV[lym][lxp];
        float a10 = sV[lyc][lxm],                     a12 = sV[lyc][lxp];
        float a20 = sV[lyp][lxm], a21 = sV[lyp][lxc], a22 = sV[lyp][lxp];

        float gxv = (a02 - a00) + 2.f * (a12 - a10) + (a22 - a20);
        float gyv = (a20 - a00) + 2.f * (a21 - a01) + (a22 - a02);

        float mag = sqrtf(gxv * gxv + gyv * gyv + 1e-6f);

        float ax = fabsf(gxv), ay = fabsf(gyv);
        int d;
        if (ay <= TAN22 * ax)      d = (gxv >= 0.f) ? 0 : 4;
        else if (ay >= TAN67 * ax) d = (gyv >= 0.f) ? 2 : 6;
        else {
            if (gxv > 0.f) d = (gyv > 0.f) ? 1 : 7;
            else           d = (gyv > 0.f) ? 3 : 5;
        }
        sM[r][c] = mag;
        sD[r][c] = (unsigned char)d;
    }
    __syncthreads();

    const int lx = threadIdx.x, ly = threadIdx.y;
    const int gx = tileX + lx, gy = tileY + ly;
    const unsigned gid = b * IMG + gy * W + gx;
    unsigned char st;
    {
        float m = sM[ly + 1][lx + 1];
        int d  = sD[ly + 1][lx + 1];
        int dn = (d + 4) & 7;

        int y1 = gy + c_dy[d],  x1 = gx + c_dx[d];
        int y2 = gy + c_dy[dn], x2 = gx + c_dx[dn];
        float n1 = (y1 >= 0 && y1 < H && x1 >= 0 && x1 < W)
                   ? sM[ly + 1 + c_dy[d]][lx + 1 + c_dx[d]] : 0.f;
        float n2 = (y2 >= 0 && y2 < H && x2 >= 0 && x2 < W)
                   ? sM[ly + 1 + c_dy[dn]][lx + 1 + c_dx[dn]] : 0.f;

        bool keep = (m > n1) && (m > n2);
        float mo = keep ? m : 0.f;
        magOut[gid] = mo;
        st = mo > 0.2f ? 2 : (mo > 0.1f ? 1 : 0);
    }

    // local CCL with reduced unions (Playne-Hawick style)
    const unsigned lid = tid;
    ls[lid] = st;
    lp[lid] = lid;
    sflag[lid] = 0;
    __syncthreads();

    if (st) {
        bool up = (ly > 0) && ls[lid - 32];
        bool ul = (ly > 0) && (lx > 0)  && ls[lid - 33];
        bool ur = (ly > 0) && (lx < 31) && ls[lid - 31];
        bool lf = (lx > 0) && ls[lid - 1];
        if (up) lunion(lp, lid, lid - 32);
        else {
            if (ul) lunion(lp, lid, lid - 33);
            if (ur) lunion(lp, lid, lid - 31);
        }
        if (lf && !(up && ul)) lunion(lp, lid, lid - 1);
    }
    __syncthreads();

    unsigned r = 0;
    if (st) {
        r = lfind(lp, lid);
        if (st == 2) sflag[r] = 1;   // only 1s written: benign race
    }
    __syncthreads();

    g_pack[gid] = st ? (unsigned short)(((unsigned)st << 14) | r) : 0;
    if (st && r == lid) {
        g_parent[gid] = gid;
        g_flag[gid]   = sflag[lid];
        unsigned slot = atomicAdd(&scnt, 1u);
        if (slot < MAXROOTS) g_roots[tileId * MAXROOTS + slot] = (unsigned short)lid;
    }
    __syncthreads();
    if (tid == 0) g_cnt[tileId] = min(scnt, (unsigned)MAXROOTS);
}

// ================= cross-tile border unions (well-founded reduction) ==========
#define VB_PER 31744u              // 31 seams * 1024
#define VB_TOT (4u * VB_PER)

__global__ void k_merge_border() {
    unsigned id = blockIdx.x * blockDim.x + threadIdx.x;
    bool vert = id < VB_TOT;
    unsigned t = vert ? id : id - VB_TOT;
    unsigned b = t / VB_PER;
    unsigned r = t % VB_PER;

    if (vert) {
        unsigned c = r >> 10;
        unsigned y = r & 1023;
        unsigned x = (c + 1) << 5;
        unsigned i = b * IMG + y * W + x;
        unsigned pki = g_pack[i];
        if (!(pki >> 14)) return;
        unsigned ri = rootPos(i, pki);

        unsigned pkL = g_pack[i - 1];
        bool bL = (pkL >> 14) != 0;
        unsigned pkP = 0, pkUL = 0;
        bool bP = false, bUL = false;
        if (y > 0) {
            pkP  = g_pack[i - W];     bP  = (pkP  >> 14) != 0;
            pkUL = g_pack[i - W - 1]; bUL = (pkUL >> 14) != 0;
        }
        bool pP = bP;
        if (bL) {
            if (!(pP && bUL)) gunion(ri, rootPos(i - 1, pkL));
        } else {
            if (bUL && !pP) gunion(ri, rootPos(i - W - 1, pkUL));
            if (y < H - 1) {
                unsigned pkDL = g_pack[i + W - 1];
                if (pkDL >> 14) gunion(ri, rootPos(i + W - 1, pkDL));
            }
        }
    } else {
        unsigned rr = r >> 10;
        unsigned x = r & 1023;
        unsigned y = (rr + 1) << 5;
        unsigned i = b * IMG + y * W + x;
        unsigned pki = g_pack[i];
        if (!(pki >> 14)) return;
        unsigned ri = rootPos(i, pki);

        unsigned pkU = g_pack[i - W];
        bool bU = (pkU >> 14) != 0;
        bool intra = (x & 31u) != 0;
        unsigned pkL = 0, pkUL = 0;
        bool bL = false, bUL = false;
        if (x > 0) {
            pkL  = g_pack[i - 1];     bL  = (pkL  >> 14) != 0;
            pkUL = g_pack[i - W - 1]; bUL = (pkUL >> 14) != 0;
        }
        bool skip = intra && bL && bUL;
        if (bU) {
            if (!skip) gunion(ri, rootPos(i - W, pkU));
        } else {
            if (bUL && !(intra && bL)) gunion(ri, rootPos(i - W - 1, pkUL));
            if (x < W - 1) {
                unsigned pkUR = g_pack[i - W + 1];
                if (pkUR >> 14) gunion(ri, rootPos(i - W + 1, pkUR));
            }
        }
    }
}

// ================= flatten roots + OR strong flag to global root =================
__global__ void k_flatten() {
    unsigned tile = blockIdx.x;
    unsigned cnt  = g_cnt[tile];
    unsigned b    = tile >> 10;
    unsigned by   = (tile >> 5) & 31u;
    unsigned bx   = tile & 31u;
    unsigned base = (b << 20) + ((by << 5) << 10) + (bx << 5);
    for (unsigned s = threadIdx.x; s < cnt; s += blockDim.x) {
        unsigned l = g_roots[tile * MAXROOTS + s];
        unsigned pos = base + ((l >> 5) << 10) + (l & 31u);
        unsigned rt = gfind(pos);
        g_parent[pos] = rt;
        if (rt != pos && g_flag[pos]) g_flag[rt] = 1;
    }
}

// ================= final: tile-cooperative flag LUT, then smem lookup =========
__global__ __launch_bounds__(1024) void k_final(float* __restrict__ edgeOut) {
    __shared__ unsigned char sLUT[1024];

    const unsigned tid = threadIdx.y * 32 + threadIdx.x;
    const unsigned tileId = ((unsigned)blockIdx.z * 32 + blockIdx.y) * 32 + blockIdx.x;
    const unsigned cnt = g_cnt[tileId];
    const unsigned base = ((unsigned)blockIdx.z << 20)
                        + ((blockIdx.y << 5) << 10) + (blockIdx.x << 5);

    // resolve each local root's flag once (cnt <= 512, block has 1024 threads)
    if (tid < cnt) {
        unsigned l   = g_roots[tileId * MAXROOTS + tid];
        unsigned pos = base + ((l >> 5) << 10) + (l & 31u);
        unsigned rt  = __ldcg(&g_parent[pos]);
        unsigned p   = __ldcg(&g_parent[rt]);
        while (p != rt) { rt = p; p = __ldcg(&g_parent[rt]); }  // usually 0 iters
        sLUT[l] = g_flag[rt];
    }
    __syncthreads();

    unsigned gx = blockIdx.x * 32 + threadIdx.x;
    unsigned gy = blockIdx.y * 32 + threadIdx.y;
    unsigned i  = ((unsigned)blockIdx.z << 20) + (gy << 10) + gx;
    unsigned pk = g_pack[i];
    float v = 0.f;
    if (pk >> 14) v = sLUT[pk & 1023u] ? 1.f : 0.f;
    edgeOut[i] = v;
}

// ---------------- launch ----------------
extern "C" void kernel_launch(void* const* d_in, const int* in_sizes, int n_in,
                              void* d_out, int out_size) {
    const float* x = (const float*)d_in[0];
    float* magOut  = (float*)d_out;
    float* edgeOut = magOut + (size_t)NPIX;

    dim3 fblk(TX, TY, 1);
    dim3 fgrd(W / TX, H / TY, BATCH);
    k_fused<<<fgrd, fblk>>>(x, magOut);

    unsigned nborder = 2u * VB_TOT;
    k_merge_border<<<(nborder + 255) / 256, 256>>>();

    k_flatten<<<NTILES, 128>>>();

    dim3 eblk(32, 32, 1);
    dim3 egrd(W / 32, H / 32, BATCH);
    k_final<<<egrd, eblk>>>(edgeOut);
}

// round 9
// speedup vs baseline: 1.0655x; 1.0655x over previous
#include <cuda_runtime.h>

#define BATCH 4
#define H 1024
#define W 1024
#define IMG (H * W)
#define NPIX (BATCH * IMG)
#define NTILES (BATCH * 32 * 32)
#define MAXROOTS 512

// ---------------- scratch ----------------
__device__ unsigned short g_pack[NPIX];   // bits[14:16)=state, bits[0:10)=local root idx
__device__ unsigned int   g_parent[NPIX]; // valid ONLY at local-root positions
__device__ unsigned char  g_flag[NPIX];   // valid ONLY at root positions
__device__ unsigned short g_roots[NTILES * MAXROOTS];
__device__ unsigned int   g_cnt[NTILES];

__constant__ int c_dy[8] = { 0, 1, 1, 1, 0, -1, -1, -1 };
__constant__ int c_dx[8] = { 1, 1, 0, -1, -1, -1, 0, 1 };

#define GW0 0.40261994f
#define GW1 0.24420134f
#define GW2 0.05448868f
#define TAN22 0.41421356237309503f
#define TAN67 2.4142135623730951f

__device__ __forceinline__ int reflect_idx(int i, int n) {
    if (i < 0) return -i;
    if (i >= n) return 2 * n - 2 - i;
    return i;
}

// ---- shared-memory union-find ----
__device__ __forceinline__ unsigned lfind(unsigned* p, unsigned i) {
    volatile unsigned* vp = (volatile unsigned*)p;
    unsigned q = vp[i];
    while (q != i) {
        unsigned qq = vp[q];
        if (qq != q) vp[i] = qq;
        i = q; q = qq;
    }
    return i;
}
__device__ __forceinline__ void lunion(unsigned* p, unsigned a, unsigned b) {
    while (true) {
        a = lfind(p, a);
        b = lfind(p, b);
        if (a == b) return;
        unsigned lo = min(a, b), hi = max(a, b);
        unsigned old = atomicCAS(&p[hi], hi, lo);
        if (old == hi) return;
        a = lo; b = old;
    }
}

// ---- global union-find (root positions only) ----
__device__ __forceinline__ unsigned gfind(unsigned i) {
    unsigned p = __ldcg(&g_parent[i]);
    while (p != i) {
        unsigned gp = __ldcg(&g_parent[p]);
        if (gp != p) __stcg(&g_parent[i], gp);
        i = p; p = gp;
    }
    return i;
}
__device__ __forceinline__ void gunion(unsigned a, unsigned b) {
    while (true) {
        a = gfind(a);
        b = gfind(b);
        if (a == b) return;
        unsigned lo = min(a, b), hi = max(a, b);
        unsigned old = atomicCAS(&g_parent[hi], hi, lo);
        if (old == hi) return;
        a = lo; b = old;
    }
}

__device__ __forceinline__ unsigned rootPos(unsigned j, unsigned pk) {
    unsigned l = pk & 1023u;
    unsigned b = j >> 20;
    unsigned y = (j >> 10) & 1023u;
    unsigned x = j & 1023u;
    return (b << 20) + (((y & ~31u) + (l >> 5)) << 10) + (x & ~31u) + (l & 31u);
}

// ================= fused stencil + NMS + threshold + local CCL =================
#define TX 32
#define TY 32

__global__ __launch_bounds__(1024) void k_fused(const float* __restrict__ x,
                                                float* __restrict__ magOut) {
    __shared__ float sG[40][41];
    __shared__ float sH[40][37];
    __shared__ float sV[36][37];
    __shared__ float sM[34][35];
    __shared__ unsigned char sD[34][35];
    __shared__ unsigned      lp[1024];
    __shared__ unsigned char ls[1024];
    __shared__ unsigned char sflag[1024];
    __shared__ unsigned scnt;

    const int tileX = blockIdx.x * TX;
    const int tileY = blockIdx.y * TY;
    const int b     = blockIdx.z;
    const int tid   = threadIdx.y * TX + threadIdx.x;
    const unsigned tileId = ((unsigned)b * 32 + blockIdx.y) * 32 + blockIdx.x;
    const float* base = x + (size_t)b * 3 * IMG;
    const bool interior = (tileX >= 4) && (tileX + 36 <= W) &&
                          (tileY >= 4) && (tileY + 36 <= H);

    if (tid == 0) scnt = 0;

    if (interior) {
        for (int idx = tid; idx < 40 * 40; idx += 1024) {
            int r = idx / 40, c = idx % 40;
            int o = (tileY - 4 + r) * W + (tileX - 4 + c);
            sG[r][c] = 0.299f * base[o] + 0.587f * base[IMG + o] + 0.114f * base[2 * IMG + o];
        }
    } else {
        for (int idx = tid; idx < 40 * 40; idx += 1024) {
            int r = idx / 40, c = idx % 40;
            int yy = reflect_idx(tileY - 4 + r, H);
            int xx = reflect_idx(tileX - 4 + c, W);
            int o = yy * W + xx;
            sG[r][c] = 0.299f * base[o] + 0.587f * base[IMG + o] + 0.114f * base[2 * IMG + o];
        }
    }
    __syncthreads();

    {
        const float w[5] = { GW2, GW1, GW0, GW1, GW2 };
        if (interior) {
            for (int idx = tid; idx < 40 * 36; idx += 1024) {
                int r = idx / 36, c = idx % 36;
                float s = 0.f;
#pragma unroll
                for (int k = 0; k < 5; k++) s += w[k] * sG[r][c + k];
                sH[r][c] = s;
            }
        } else {
            for (int idx = tid; idx < 40 * 36; idx += 1024) {
                int r = idx / 36, c = idx % 36;
                int gx = tileX - 2 + c;
                float s = 0.f;
#pragma unroll
                for (int k = 0; k < 5; k++) {
                    int lx = reflect_idx(gx + k - 2, W) - (tileX - 4);
                    s += w[k] * sG[r][lx];
                }
                sH[r][c] = s;
            }
        }
    }
    __syncthreads();

    {
        const float w[5] = { GW2, GW1, GW0, GW1, GW2 };
        if (interior) {
            for (int idx = tid; idx < 36 * 36; idx += 1024) {
                int r = idx / 36, c = idx % 36;
                float s = 0.f;
#pragma unroll
                for (int k = 0; k < 5; k++) s += w[k] * sH[r + k][c];
                sV[r][c] = s;
            }
        } else {
            for (int idx = tid; idx < 36 * 36; idx += 1024) {
                int r = idx / 36, c = idx % 36;
                int gy = tileY - 2 + r;
                float s = 0.f;
#pragma unroll
                for (int k = 0; k < 5; k++) {
                    int ly = reflect_idx(gy + k - 2, H) - (tileY - 4);
                    s += w[k] * sH[ly][c];
                }
                sV[r][c] = s;
            }
        }
    }
    __syncthreads();

    for (int idx = tid; idx < 34 * 34; idx += 1024) {
        int r = idx / 34, c = idx % 34;
        float a00, a01, a02, a10, a12, a20, a21, a22;
        if (interior) {
            a00 = sV[r][c];     a01 = sV[r][c + 1];     a02 = sV[r][c + 2];
            a10 = sV[r + 1][c];                         a12 = sV[r + 1][c + 2];
            a20 = sV[r + 2][c]; a21 = sV[r + 2][c + 1]; a22 = sV[r + 2][c + 2];
        } else {
            int gy = tileY - 1 + r;
            int gx = tileX - 1 + c;
            int xm = max(gx - 1, 0), xp = min(gx + 1, W - 1);
            int ym = max(gy - 1, 0), yp = min(gy + 1, H - 1);
            int xc = min(max(gx, 0), W - 1), yc = min(max(gy, 0), H - 1);
            int lxm = xm - (tileX - 2), lxp = xp - (tileX - 2), lxc = xc - (tileX - 2);
            int lym = ym - (tileY - 2), lyp = yp - (tileY - 2), lyc = yc - (tileY - 2);
            a00 = sV[lym][lxm]; a01 = sV[lym][lxc]; a02 = sV[lym][lxp];
            a10 = sV[lyc][lxm];                     a12 = sV[lyc][lxp];
            a20 = sV[lyp][lxm]; a21 = sV[lyp][lxc]; a22 = sV[lyp][lxp];
        }

        float gxv = (a02 - a00) + 2.f * (a12 - a10) + (a22 - a20);
        float gyv = (a20 - a00) + 2.f * (a21 - a01) + (a22 - a02);

        float mag = sqrtf(gxv * gxv + gyv * gyv + 1e-6f);

        float ax = fabsf(gxv), ay = fabsf(gyv);
        int d;
        if (ay <= TAN22 * ax)      d = (gxv >= 0.f) ? 0 : 4;
        else if (ay >= TAN67 * ax) d = (gyv >= 0.f) ? 2 : 6;
        else {
            if (gxv > 0.f) d = (gyv > 0.f) ? 1 : 7;
            else           d = (gyv > 0.f) ? 3 : 5;
        }
        sM[r][c] = mag;
        sD[r][c] = (unsigned char)d;
    }
    __syncthreads();

    const int lx = threadIdx.x, ly = threadIdx.y;
    const int gx = tileX + lx, gy = tileY + ly;
    const unsigned gid = b * IMG + gy * W + gx;
    unsigned char st;
    {
        float m = sM[ly + 1][lx + 1];
        int d  = sD[ly + 1][lx + 1];
        int dn = (d + 4) & 7;

        float n1, n2;
        if (interior) {
            n1 = sM[ly + 1 + c_dy[d]][lx + 1 + c_dx[d]];
            n2 = sM[ly + 1 + c_dy[dn]][lx + 1 + c_dx[dn]];
        } else {
            int y1 = gy + c_dy[d],  x1 = gx + c_dx[d];
            int y2 = gy + c_dy[dn], x2 = gx + c_dx[dn];
            n1 = (y1 >= 0 && y1 < H && x1 >= 0 && x1 < W)
                 ? sM[ly + 1 + c_dy[d]][lx + 1 + c_dx[d]] : 0.f;
            n2 = (y2 >= 0 && y2 < H && x2 >= 0 && x2 < W)
                 ? sM[ly + 1 + c_dy[dn]][lx + 1 + c_dx[dn]] : 0.f;
        }

        bool keep = (m > n1) && (m > n2);
        float mo = keep ? m : 0.f;
        magOut[gid] = mo;
        st = mo > 0.2f ? 2 : (mo > 0.1f ? 1 : 0);
    }

    // local CCL with reduced unions
    const unsigned lid = tid;
    ls[lid] = st;
    lp[lid] = lid;
    sflag[lid] = 0;
    __syncthreads();

    if (st) {
        bool up = (ly > 0) && ls[lid - 32];
        bool ul = (ly > 0) && (lx > 0)  && ls[lid - 33];
        bool ur = (ly > 0) && (lx < 31) && ls[lid - 31];
        bool lf = (lx > 0) && ls[lid - 1];
        if (up) lunion(lp, lid, lid - 32);
        else {
            if (ul) lunion(lp, lid, lid - 33);
            if (ur) lunion(lp, lid, lid - 31);
        }
        if (lf && !(up && ul)) lunion(lp, lid, lid - 1);
    }
    __syncthreads();

    unsigned r = 0;
    if (st) {
        r = lfind(lp, lid);
        if (st == 2) sflag[r] = 1;
    }
    __syncthreads();

    g_pack[gid] = st ? (unsigned short)(((unsigned)st << 14) | r) : 0;
    if (st && r == lid) {
        g_parent[gid] = gid;
        g_flag[gid]   = sflag[lid];
        unsigned slot = atomicAdd(&scnt, 1u);
        if (slot < MAXROOTS) g_roots[tileId * MAXROOTS + slot] = (unsigned short)lid;
    }
    __syncthreads();
    if (tid == 0) g_cnt[tileId] = min(scnt, (unsigned)MAXROOTS);
}

// ================= cross-tile border unions (well-founded reduction) ==========
#define VB_PER 31744u
#define VB_TOT (4u * VB_PER)

__global__ void k_merge_border() {
    unsigned id = blockIdx.x * blockDim.x + threadIdx.x;
    bool vert = id < VB_TOT;
    unsigned t = vert ? id : id - VB_TOT;
    unsigned b = t / VB_PER;
    unsigned r = t % VB_PER;

    if (vert) {
        unsigned c = r >> 10;
        unsigned y = r & 1023;
        unsigned x = (c + 1) << 5;
        unsigned i = b * IMG + y * W + x;
        unsigned pki = g_pack[i];
        if (!(pki >> 14)) return;
        unsigned ri = rootPos(i, pki);

        unsigned pkL = g_pack[i - 1];
        bool bL = (pkL >> 14) != 0;
        unsigned pkP = 0, pkUL = 0;
        bool bP = false, bUL = false;
        if (y > 0) {
            pkP  = g_pack[i - W];     bP  = (pkP  >> 14) != 0;
            pkUL = g_pack[i - W - 1]; bUL = (pkUL >> 14) != 0;
        }
        bool pP = bP;
        if (bL) {
            if (!(pP && bUL)) gunion(ri, rootPos(i - 1, pkL));
        } else {
            if (bUL && !pP) gunion(ri, rootPos(i - W - 1, pkUL));
            if (y < H - 1) {
                unsigned pkDL = g_pack[i + W - 1];
                if (pkDL >> 14) gunion(ri, rootPos(i + W - 1, pkDL));
            }
        }
    } else {
        unsigned rr = r >> 10;
        unsigned x = r & 1023;
        unsigned y = (rr + 1) << 5;
        unsigned i = b * IMG + y * W + x;
        unsigned pki = g_pack[i];
        if (!(pki >> 14)) return;
        unsigned ri = rootPos(i, pki);

        unsigned pkU = g_pack[i - W];
        bool bU = (pkU >> 14) != 0;
        bool intra = (x & 31u) != 0;
        unsigned pkL = 0, pkUL = 0;
        bool bL = false, bUL = false;
        if (x > 0) {
            pkL  = g_pack[i - 1];     bL  = (pkL  >> 14) != 0;
            pkUL = g_pack[i - W - 1]; bUL = (pkUL >> 14) != 0;
        }
        bool skip = intra && bL && bUL;
        if (bU) {
            if (!skip) gunion(ri, rootPos(i - W, pkU));
        } else {
            if (bUL && !(intra && bL)) gunion(ri, rootPos(i - W - 1, pkUL));
            if (x < W - 1) {
                unsigned pkUR = g_pack[i - W + 1];
                if (pkUR >> 14) gunion(ri, rootPos(i - W + 1, pkUR));
            }
        }
    }
}

// ================= flatten roots + OR strong flag to global root =================
__global__ void k_flatten() {
    unsigned tile = blockIdx.x;
    unsigned cnt  = g_cnt[tile];
    unsigned b    = tile >> 10;
    unsigned by   = (tile >> 5) & 31u;
    unsigned bx   = tile & 31u;
    unsigned base = (b << 20) + ((by << 5) << 10) + (bx << 5);
    for (unsigned s = threadIdx.x; s < cnt; s += blockDim.x) {
        unsigned l = g_roots[tile * MAXROOTS + s];
        unsigned pos = base + ((l >> 5) << 10) + (l & 31u);
        unsigned rt = gfind(pos);
        g_parent[pos] = rt;
        if (rt != pos && g_flag[pos]) g_flag[rt] = 1;
    }
}

// ================= final: per-pixel with 4-way ILP =================
__global__ __launch_bounds__(256) void k_final(float* __restrict__ edgeOut) {
    const unsigned gx = blockIdx.x * 32 + threadIdx.x;
    const unsigned bz = blockIdx.z;
    const unsigned baseTile = (bz << 20) + ((blockIdx.y << 5) << 10) + (blockIdx.x << 5);

    unsigned idx[4], pk[4], rt[4];
#pragma unroll
    for (int k = 0; k < 4; k++) {
        unsigned gy = blockIdx.y * 32 + threadIdx.y + 8 * k;
        idx[k] = (bz << 20) + (gy << 10) + gx;
        pk[k]  = g_pack[idx[k]];
    }
#pragma unroll
    for (int k = 0; k < 4; k++) {
        if (pk[k] >> 14) {
            unsigned l = pk[k] & 1023u;
            unsigned pos = baseTile + ((l >> 5) << 10) + (l & 31u);
            rt[k] = __ldcg(&g_parent[pos]);
        }
    }
#pragma unroll
    for (int k = 0; k < 4; k++) {
        if (pk[k] >> 14) {
            unsigned p = __ldcg(&g_parent[rt[k]]);
            while (p != rt[k]) { rt[k] = p; p = __ldcg(&g_parent[rt[k]]); }
        }
    }
#pragma unroll
    for (int k = 0; k < 4; k++) {
        float v = 0.f;
        if (pk[k] >> 14) v = g_flag[rt[k]] ? 1.f : 0.f;
        edgeOut[idx[k]] = v;
    }
}

// ---------------- launch ----------------
extern "C" void kernel_launch(void* const* d_in, const int* in_sizes, int n_in,
                              void* d_out, int out_size) {
    const float* x = (const float*)d_in[0];
    float* magOut  = (float*)d_out;
    float* edgeOut = magOut + (size_t)NPIX;

    dim3 fblk(TX, TY, 1);
    dim3 fgrd(W / TX, H / TY, BATCH);
    k_fused<<<fgrd, fblk>>>(x, magOut);

    unsigned nborder = 2u * VB_TOT;
    k_merge_border<<<(nborder + 255) / 256, 256>>>();

    k_flatten<<<NTILES, 128>>>();

    dim3 eblk(32, 8, 1);
    dim3 egrd(W / 32, H / 32, BATCH);
    k_final<<<egrd, eblk>>>(edgeOut);
}

// round 10
// speedup vs baseline: 1.1014x; 1.0336x over previous
#include <cuda_runtime.h>

#define BATCH 4
#define H 1024
#define W 1024
#define IMG (H * W)
#define NPIX (BATCH * IMG)
#define NTILES (BATCH * 32 * 32)
#define MAXROOTS 512

// ---------------- scratch ----------------
__device__ unsigned short g_pack[NPIX];   // bits[14:16)=state, bits[0:10)=local root idx
__device__ unsigned int   g_parent[NPIX]; // valid ONLY at local-root positions
__device__ unsigned char  g_flag[NPIX];   // at global-root positions: component-has-strong
__device__ unsigned char  g_flagL[NPIX];  // at local-root positions: RESOLVED flag
__device__ unsigned short g_roots[NTILES * MAXROOTS];
__device__ unsigned int   g_cnt[NTILES];

__constant__ int c_dy[8] = { 0, 1, 1, 1, 0, -1, -1, -1 };
__constant__ int c_dx[8] = { 1, 1, 0, -1, -1, -1, 0, 1 };

#define GW0 0.40261994f
#define GW1 0.24420134f
#define GW2 0.05448868f
#define TAN22 0.41421356237309503f
#define TAN67 2.4142135623730951f

__device__ __forceinline__ int reflect_idx(int i, int n) {
    if (i < 0) return -i;
    if (i >= n) return 2 * n - 2 - i;
    return i;
}

// ---- shared-memory union-find ----
__device__ __forceinline__ unsigned lfind(unsigned* p, unsigned i) {
    volatile unsigned* vp = (volatile unsigned*)p;
    unsigned q = vp[i];
    while (q != i) {
        unsigned qq = vp[q];
        if (qq != q) vp[i] = qq;
        i = q; q = qq;
    }
    return i;
}
__device__ __forceinline__ void lunion(unsigned* p, unsigned a, unsigned b) {
    while (true) {
        a = lfind(p, a);
        b = lfind(p, b);
        if (a == b) return;
        unsigned lo = min(a, b), hi = max(a, b);
        unsigned old = atomicCAS(&p[hi], hi, lo);
        if (old == hi) return;
        a = lo; b = old;
    }
}

// ---- global union-find (root positions only) ----
__device__ __forceinline__ unsigned gfind(unsigned i) {
    unsigned p = __ldcg(&g_parent[i]);
    while (p != i) {
        unsigned gp = __ldcg(&g_parent[p]);
        if (gp != p) __stcg(&g_parent[i], gp);
        i = p; p = gp;
    }
    return i;
}
__device__ __forceinline__ void gunion(unsigned a, unsigned b) {
    while (true) {
        a = gfind(a);
        b = gfind(b);
        if (a == b) return;
        unsigned lo = min(a, b), hi = max(a, b);
        unsigned old = atomicCAS(&g_parent[hi], hi, lo);
        if (old == hi) return;
        a = lo; b = old;
    }
}

__device__ __forceinline__ unsigned rootPos(unsigned j, unsigned pk) {
    unsigned l = pk & 1023u;
    unsigned b = j >> 20;
    unsigned y = (j >> 10) & 1023u;
    unsigned x = j & 1023u;
    return (b << 20) + (((y & ~31u) + (l >> 5)) << 10) + (x & ~31u) + (l & 31u);
}

// ================= fused stencil + NMS + threshold + local CCL =================
// shared memory is phase-aliased to fit 2 blocks/SM:
//   [0, 6560)      sG (float[40][41])  -> sM (float[34][35]) -> lp/ls/sflag
//   [6560, 12480)  sH (float[40][37])  -> sD (uchar[34][35])
//   [12480, 17808) sV (float[36][37])
#define TX 32
#define TY 32
#define OFF_H 6560
#define OFF_V 12480
#define SMEM_BYTES 17808

__global__ __launch_bounds__(1024, 2) void k_fused(const float* __restrict__ x,
                                                   float* __restrict__ magOut) {
    __shared__ __align__(16) unsigned char sbuf[SMEM_BYTES];
    __shared__ unsigned scnt;

    float (*sG)[41] = (float(*)[41])(sbuf);
    float (*sH)[37] = (float(*)[37])(sbuf + OFF_H);
    float (*sV)[37] = (float(*)[37])(sbuf + OFF_V);
    float (*sM)[35] = (float(*)[35])(sbuf);                       // aliases sG
    unsigned char (*sD)[35] = (unsigned char(*)[35])(sbuf + OFF_H); // aliases sH
    unsigned*      lp    = (unsigned*)(sbuf);                     // aliases sM (post-sync)
    unsigned char* ls    = sbuf + 4096;
    unsigned char* sflag = sbuf + 5120;

    const int tileX = blockIdx.x * TX;
    const int tileY = blockIdx.y * TY;
    const int b     = blockIdx.z;
    const int tid   = threadIdx.y * TX + threadIdx.x;
    const unsigned tileId = ((unsigned)b * 32 + blockIdx.y) * 32 + blockIdx.x;
    const float* base = x + (size_t)b * 3 * IMG;
    const bool interior = (tileX >= 4) && (tileX + 36 <= W) &&
                          (tileY >= 4) && (tileY + 36 <= H);

    if (tid == 0) scnt = 0;

    if (interior) {
        for (int idx = tid; idx < 40 * 40; idx += 1024) {
            int r = idx / 40, c = idx % 40;
            int o = (tileY - 4 + r) * W + (tileX - 4 + c);
            sG[r][c] = 0.299f * base[o] + 0.587f * base[IMG + o] + 0.114f * base[2 * IMG + o];
        }
    } else {
        for (int idx = tid; idx < 40 * 40; idx += 1024) {
            int r = idx / 40, c = idx % 40;
            int yy = reflect_idx(tileY - 4 + r, H);
            int xx = reflect_idx(tileX - 4 + c, W);
            int o = yy * W + xx;
            sG[r][c] = 0.299f * base[o] + 0.587f * base[IMG + o] + 0.114f * base[2 * IMG + o];
        }
    }
    __syncthreads();

    {
        const float w[5] = { GW2, GW1, GW0, GW1, GW2 };
        if (interior) {
            for (int idx = tid; idx < 40 * 36; idx += 1024) {
                int r = idx / 36, c = idx % 36;
                float s = 0.f;
#pragma unroll
                for (int k = 0; k < 5; k++) s += w[k] * sG[r][c + k];
                sH[r][c] = s;
            }
        } else {
            for (int idx = tid; idx < 40 * 36; idx += 1024) {
                int r = idx / 36, c = idx % 36;
                int gx = tileX - 2 + c;
                float s = 0.f;
#pragma unroll
                for (int k = 0; k < 5; k++) {
                    int lx = reflect_idx(gx + k - 2, W) - (tileX - 4);
                    s += w[k] * sG[r][lx];
                }
                sH[r][c] = s;
            }
        }
    }
    __syncthreads();   // sG dead after this point

    {
        const float w[5] = { GW2, GW1, GW0, GW1, GW2 };
        if (interior) {
            for (int idx = tid; idx < 36 * 36; idx += 1024) {
                int r = idx / 36, c = idx % 36;
                float s = 0.f;
#pragma unroll
                for (int k = 0; k < 5; k++) s += w[k] * sH[r + k][c];
                sV[r][c] = s;
            }
        } else {
            for (int idx = tid; idx < 36 * 36; idx += 1024) {
                int r = idx / 36, c = idx % 36;
                int gy = tileY - 2 + r;
                float s = 0.f;
#pragma unroll
                for (int k = 0; k < 5; k++) {
                    int ly = reflect_idx(gy + k - 2, H) - (tileY - 4);
                    s += w[k] * sH[ly][c];
                }
                sV[r][c] = s;
            }
        }
    }
    __syncthreads();   // sH dead; sM (over sG) and sD (over sH) now writable

    for (int idx = tid; idx < 34 * 34; idx += 1024) {
        int r = idx / 34, c = idx % 34;
        float a00, a01, a02, a10, a12, a20, a21, a22;
        if (interior) {
            a00 = sV[r][c];     a01 = sV[r][c + 1];     a02 = sV[r][c + 2];
            a10 = sV[r + 1][c];                         a12 = sV[r + 1][c + 2];
            a20 = sV[r + 2][c]; a21 = sV[r + 2][c + 1]; a22 = sV[r + 2][c + 2];
        } else {
            int gy = tileY - 1 + r;
            int gx = tileX - 1 + c;
            int xm = max(gx - 1, 0), xp = min(gx + 1, W - 1);
            int ym = max(gy - 1, 0), yp = min(gy + 1, H - 1);
            int xc = min(max(gx, 0), W - 1), yc = min(max(gy, 0), H - 1);
            int lxm = xm - (tileX - 2), lxp = xp - (tileX - 2), lxc = xc - (tileX - 2);
            int lym = ym - (tileY - 2), lyp = yp - (tileY - 2), lyc = yc - (tileY - 2);
            a00 = sV[lym][lxm]; a01 = sV[lym][lxc]; a02 = sV[lym][lxp];
            a10 = sV[lyc][lxm];                     a12 = sV[lyc][lxp];
            a20 = sV[lyp][lxm]; a21 = sV[lyp][lxc]; a22 = sV[lyp][lxp];
        }

        float gxv = (a02 - a00) + 2.f * (a12 - a10) + (a22 - a20);
        float gyv = (a20 - a00) + 2.f * (a21 - a01) + (a22 - a02);

        float mag = sqrtf(gxv * gxv + gyv * gyv + 1e-6f);

        float ax = fabsf(gxv), ay = fabsf(gyv);
        int d;
        if (ay <= TAN22 * ax)      d = (gxv >= 0.f) ? 0 : 4;
        else if (ay >= TAN67 * ax) d = (gyv >= 0.f) ? 2 : 6;
        else {
            if (gxv > 0.f) d = (gyv > 0.f) ? 1 : 7;
            else           d = (gyv > 0.f) ? 3 : 5;
        }
        sM[r][c] = mag;
        sD[r][c] = (unsigned char)d;
    }
    __syncthreads();

    const int lx = threadIdx.x, ly = threadIdx.y;
    const int gx = tileX + lx, gy = tileY + ly;
    const unsigned gid = b * IMG + gy * W + gx;
    unsigned char st;
    {
        float m = sM[ly + 1][lx + 1];
        int d  = sD[ly + 1][lx + 1];
        int dn = (d + 4) & 7;

        float n1, n2;
        if (interior) {
            n1 = sM[ly + 1 + c_dy[d]][lx + 1 + c_dx[d]];
            n2 = sM[ly + 1 + c_dy[dn]][lx + 1 + c_dx[dn]];
        } else {
            int y1 = gy + c_dy[d],  x1 = gx + c_dx[d];
            int y2 = gy + c_dy[dn], x2 = gx + c_dx[dn];
            n1 = (y1 >= 0 && y1 < H && x1 >= 0 && x1 < W)
                 ? sM[ly + 1 + c_dy[d]][lx + 1 + c_dx[d]] : 0.f;
            n2 = (y2 >= 0 && y2 < H && x2 >= 0 && x2 < W)
                 ? sM[ly + 1 + c_dy[dn]][lx + 1 + c_dx[dn]] : 0.f;
        }

        bool keep = (m > n1) && (m > n2);
        float mo = keep ? m : 0.f;
        magOut[gid] = mo;
        st = mo > 0.2f ? 2 : (mo > 0.1f ? 1 : 0);
    }
    __syncthreads();   // sM/sD dead; lp/ls/sflag (aliasing them) now writable

    // local CCL with reduced unions
    const unsigned lid = tid;
    ls[lid] = st;
    lp[lid] = lid;
    sflag[lid] = 0;
    __syncthreads();

    if (st) {
        bool up = (ly > 0) && ls[lid - 32];
        bool ul = (ly > 0) && (lx > 0)  && ls[lid - 33];
        bool ur = (ly > 0) && (lx < 31) && ls[lid - 31];
        bool lf = (lx > 0) && ls[lid - 1];
        if (up) lunion(lp, lid, lid - 32);
        else {
            if (ul) lunion(lp, lid, lid - 33);
            if (ur) lunion(lp, lid, lid - 31);
        }
        if (lf && !(up && ul)) lunion(lp, lid, lid - 1);
    }
    __syncthreads();

    unsigned r = 0;
    if (st) {
        r = lfind(lp, lid);
        if (st == 2) sflag[r] = 1;
    }
    __syncthreads();

    g_pack[gid] = st ? (unsigned short)(((unsigned)st << 14) | r) : 0;
    if (st && r == lid) {
        g_parent[gid] = gid;
        g_flag[gid]   = sflag[lid];
        unsigned slot = atomicAdd(&scnt, 1u);
        if (slot < MAXROOTS) g_roots[tileId * MAXROOTS + slot] = (unsigned short)lid;
    }
    __syncthreads();
    if (tid == 0) g_cnt[tileId] = min(scnt, (unsigned)MAXROOTS);
}

// ================= cross-tile border unions (well-founded reduction) ==========
#define VB_PER 31744u
#define VB_TOT (4u * VB_PER)

__global__ void k_merge_border() {
    unsigned id = blockIdx.x * blockDim.x + threadIdx.x;
    bool vert = id < VB_TOT;
    unsigned t = vert ? id : id - VB_TOT;
    unsigned b = t / VB_PER;
    unsigned r = t % VB_PER;

    if (vert) {
        unsigned c = r >> 10;
        unsigned y = r & 1023;
        unsigned x = (c + 1) << 5;
        unsigned i = b * IMG + y * W + x;
        unsigned pki = g_pack[i];
        if (!(pki >> 14)) return;
        unsigned ri = rootPos(i, pki);

        unsigned pkL = g_pack[i - 1];
        bool bL = (pkL >> 14) != 0;
        unsigned pkP = 0, pkUL = 0;
        bool bP = false, bUL = false;
        if (y > 0) {
            pkP  = g_pack[i - W];     bP  = (pkP  >> 14) != 0;
            pkUL = g_pack[i - W - 1]; bUL = (pkUL >> 14) != 0;
        }
        bool pP = bP;
        if (bL) {
            if (!(pP && bUL)) gunion(ri, rootPos(i - 1, pkL));
        } else {
            if (bUL && !pP) gunion(ri, rootPos(i - W - 1, pkUL));
            if (y < H - 1) {
                unsigned pkDL = g_pack[i + W - 1];
                if (pkDL >> 14) gunion(ri, rootPos(i + W - 1, pkDL));
            }
        }
    } else {
        unsigned rr = r >> 10;
        unsigned x = r & 1023;
        unsigned y = (rr + 1) << 5;
        unsigned i = b * IMG + y * W + x;
        unsigned pki = g_pack[i];
        if (!(pki >> 14)) return;
        unsigned ri = rootPos(i, pki);

        unsigned pkU = g_pack[i - W];
        bool bU = (pkU >> 14) != 0;
        bool intra = (x & 31u) != 0;
        unsigned pkL = 0, pkUL = 0;
        bool bL = false, bUL = false;
        if (x > 0) {
            pkL  = g_pack[i - 1];     bL  = (pkL  >> 14) != 0;
            pkUL = g_pack[i - W - 1]; bUL = (pkUL >> 14) != 0;
        }
        bool skip = intra && bL && bUL;
        if (bU) {
            if (!skip) gunion(ri, rootPos(i - W, pkU));
        } else {
            if (bUL && !(intra && bL)) gunion(ri, rootPos(i - W - 1, pkUL));
            if (x < W - 1) {
                unsigned pkUR = g_pack[i - W + 1];
                if (pkUR >> 14) gunion(ri, rootPos(i - W + 1, pkUR));
            }
        }
    }
}

// ================= flatten roots + OR strong flag to global root =================
__global__ void k_flatten() {
    unsigned tile = blockIdx.x;
    unsigned cnt  = g_cnt[tile];
    unsigned b    = tile >> 10;
    unsigned by   = (tile >> 5) & 31u;
    unsigned bx   = tile & 31u;
    unsigned base = (b << 20) + ((by << 5) << 10) + (bx << 5);
    for (unsigned s = threadIdx.x; s < cnt; s += blockDim.x) {
        unsigned l = g_roots[tile * MAXROOTS + s];
        unsigned pos = base + ((l >> 5) << 10) + (l & 31u);
        unsigned rt = gfind(pos);
        g_parent[pos] = rt;
        if (rt != pos && g_flag[pos]) g_flag[rt] = 1;
    }
}

// ===== push RESOLVED flag down to local roots (parent frozen => deterministic) =====
__global__ void k_flatten2() {
    unsigned tile = blockIdx.x;
    unsigned cnt  = g_cnt[tile];
    unsigned b    = tile >> 10;
    unsigned by   = (tile >> 5) & 31u;
    unsigned bx   = tile & 31u;
    unsigned base = (b << 20) + ((by << 5) << 10) + (bx << 5);
    for (unsigned s = threadIdx.x; s < cnt; s += blockDim.x) {
        unsigned l = g_roots[tile * MAXROOTS + s];
        unsigned pos = base + ((l >> 5) << 10) + (l & 31u);
        unsigned rt = __ldcg(&g_parent[pos]);
        unsigned p  = __ldcg(&g_parent[rt]);
        while (p != rt) { rt = p; p = __ldcg(&g_parent[rt]); }  // usually 0 iters
        g_flagL[pos] = g_flag[rt];
    }
}

// ================= final: 2 loads per pixel, 4-way ILP =================
__global__ __launch_bounds__(256) void k_final(float* __restrict__ edgeOut) {
    const unsigned gx = blockIdx.x * 32 + threadIdx.x;
    const unsigned bz = blockIdx.z;
    const unsigned baseTile = (bz << 20) + ((blockIdx.y << 5) << 10) + (blockIdx.x << 5);

    unsigned idx[4], pk[4];
    unsigned char fl[4];
#pragma unroll
    for (int k = 0; k < 4; k++) {
        unsigned gy = blockIdx.y * 32 + threadIdx.y + 8 * k;
        idx[k] = (bz << 20) + (gy << 10) + gx;
        pk[k]  = g_pack[idx[k]];
    }
#pragma unroll
    for (int k = 0; k < 4; k++) {
        fl[k] = 0;
        if (pk[k] >> 14) {
            unsigned l = pk[k] & 1023u;
            unsigned pos = baseTile + ((l >> 5) << 10) + (l & 31u);
            fl[k] = __ldcg(&g_flagL[pos]);
        }
    }
#pragma unroll
    for (int k = 0; k < 4; k++) {
        edgeOut[idx[k]] = fl[k] ? 1.f : 0.f;
    }
}

// ---------------- launch ----------------
extern "C" void kernel_launch(void* const* d_in, const int* in_sizes, int n_in,
                              void* d_out, int out_size) {
    const float* x = (const float*)d_in[0];
    float* magOut  = (float*)d_out;
    float* edgeOut = magOut + (size_t)NPIX;

    dim3 fblk(TX, TY, 1);
    dim3 fgrd(W / TX, H / TY, BATCH);
    k_fused<<<fgrd, fblk>>>(x, magOut);

    unsigned nborder = 2u * VB_TOT;
    k_merge_border<<<(nborder + 255) / 256, 256>>>();

    k_flatten<<<NTILES, 128>>>();
    k_flatten2<<<NTILES, 128>>>();

    dim3 eblk(32, 8, 1);
    dim3 egrd(W / 32, H / 32, BATCH);
    k_final<<<egrd, eblk>>>(edgeOut);
}

// round 11
// speedup vs baseline: 1.1371x; 1.0324x over previous
#include <cuda_runtime.h>

#define BATCH 4
#define H 1024
#define W 1024
#define IMG (H * W)
#define NPIX (BATCH * IMG)
#define TW 64
#define TH 64
#define NTX (W / TW)              // 16
#define NTY (H / TH)              // 16
#define NTILES (BATCH * NTX * NTY)  // 1024
#define MAXROOTS 1024

// ---------------- scratch ----------------
__device__ unsigned short g_pack[NPIX];   // bits[12:14)=state, bits[0:12)=local root idx
__device__ unsigned int   g_parent[NPIX]; // valid ONLY at local-root positions
__device__ unsigned char  g_flag[NPIX];   // at global-root positions
__device__ unsigned char  g_flagL[NPIX];  // at local-root positions: resolved flag
__device__ unsigned short g_roots[NTILES * MAXROOTS];
__device__ unsigned int   g_cnt[NTILES];

__constant__ int c_dy[8] = { 0, 1, 1, 1, 0, -1, -1, -1 };
__constant__ int c_dx[8] = { 1, 1, 0, -1, -1, -1, 0, 1 };

#define GW0 0.40261994f
#define GW1 0.24420134f
#define GW2 0.05448868f
#define TAN22 0.41421356237309503f
#define TAN67 2.4142135623730951f

__device__ __forceinline__ int reflect_idx(int i, int n) {
    if (i < 0) return -i;
    if (i >= n) return 2 * n - 2 - i;
    return i;
}

// ---- shared-memory union-find ----
__device__ __forceinline__ unsigned lfind(unsigned* p, unsigned i) {
    volatile unsigned* vp = (volatile unsigned*)p;
    unsigned q = vp[i];
    while (q != i) {
        unsigned qq = vp[q];
        if (qq != q) vp[i] = qq;
        i = q; q = qq;
    }
    return i;
}
__device__ __forceinline__ void lunion(unsigned* p, unsigned a, unsigned b) {
    while (true) {
        a = lfind(p, a);
        b = lfind(p, b);
        if (a == b) return;
        unsigned lo = min(a, b), hi = max(a, b);
        unsigned old = atomicCAS(&p[hi], hi, lo);
        if (old == hi) return;
        a = lo; b = old;
    }
}

// ---- global union-find (root positions only) ----
__device__ __forceinline__ unsigned gfind(unsigned i) {
    unsigned p = __ldcg(&g_parent[i]);
    while (p != i) {
        unsigned gp = __ldcg(&g_parent[p]);
        if (gp != p) __stcg(&g_parent[i], gp);
        i = p; p = gp;
    }
    return i;
}
__device__ __forceinline__ void gunion(unsigned a, unsigned b) {
    while (true) {
        a = gfind(a);
        b = gfind(b);
        if (a == b) return;
        unsigned lo = min(a, b), hi = max(a, b);
        unsigned old = atomicCAS(&g_parent[hi], hi, lo);
        if (old == hi) return;
        a = lo; b = old;
    }
}

__device__ __forceinline__ unsigned rootPos(unsigned j, unsigned pk) {
    unsigned l = pk & 4095u;
    unsigned b = j >> 20;
    unsigned y = (j >> 10) & 1023u;
    unsigned x = j & 1023u;
    return (b << 20) + (((y & ~63u) + (l >> 6)) << 10) + (x & ~63u) + (l & 63u);
}

// ================= fused stencil + NMS + threshold + local CCL =================
// smem phase-aliased layout (bytes):
//   [0, 20736)      sG f[72][72] -> sV f[68][68] -> lp u32[4096] + ls u8[4096]
//   [20736, 40320)  sH f[72][68] -> sM f[66][66] -> sflag u8[4096] (at 20736)
//   [40320, 44676)  sD u8[66][66]
#define OFF_H 20736
#define OFF_D 40320
#define SMEM_BYTES 44680

__global__ __launch_bounds__(1024, 2) void k_fused(const float* __restrict__ x,
                                                   float* __restrict__ magOut) {
    __shared__ __align__(16) unsigned char sbuf[SMEM_BYTES];
    __shared__ unsigned scnt;

    float (*sG)[72] = (float(*)[72])(sbuf);
    float (*sV)[68] = (float(*)[68])(sbuf);             // aliases sG
    float (*sH)[68] = (float(*)[68])(sbuf + OFF_H);
    float (*sM)[66] = (float(*)[66])(sbuf + OFF_H);     // aliases sH
    unsigned char (*sD)[66] = (unsigned char(*)[66])(sbuf + OFF_D);
    unsigned*      lp    = (unsigned*)(sbuf);           // aliases sV (post-sync)
    unsigned char* ls    = sbuf + 16384;
    unsigned char* sflag = sbuf + OFF_H;                // aliases sM (post-sync)

    const int tileX = blockIdx.x * TW;
    const int tileY = blockIdx.y * TH;
    const int b     = blockIdx.z;
    const int tid   = threadIdx.y * 32 + threadIdx.x;
    const unsigned tileId = ((unsigned)b * NTY + blockIdx.y) * NTX + blockIdx.x;
    const float* base = x + (size_t)b * 3 * IMG;
    const bool interior = (tileX >= 4) && (tileX + TW + 4 <= W) &&
                          (tileY >= 4) && (tileY + TH + 4 <= H);

    if (tid == 0) scnt = 0;

    // gray: 72 x 72
    if (interior) {
        for (int idx = tid; idx < 72 * 72; idx += 1024) {
            int r = idx / 72, c = idx % 72;
            int o = (tileY - 4 + r) * W + (tileX - 4 + c);
            sG[r][c] = 0.299f * base[o] + 0.587f * base[IMG + o] + 0.114f * base[2 * IMG + o];
        }
    } else {
        for (int idx = tid; idx < 72 * 72; idx += 1024) {
            int r = idx / 72, c = idx % 72;
            int yy = reflect_idx(tileY - 4 + r, H);
            int xx = reflect_idx(tileX - 4 + c, W);
            int o = yy * W + xx;
            sG[r][c] = 0.299f * base[o] + 0.587f * base[IMG + o] + 0.114f * base[2 * IMG + o];
        }
    }
    __syncthreads();

    // blurH: 72 rows x 68 cols
    {
        const float w[5] = { GW2, GW1, GW0, GW1, GW2 };
        if (interior) {
            for (int idx = tid; idx < 72 * 68; idx += 1024) {
                int r = idx / 68, c = idx % 68;
                float s = 0.f;
#pragma unroll
                for (int k = 0; k < 5; k++) s += w[k] * sG[r][c + k];
                sH[r][c] = s;
            }
        } else {
            for (int idx = tid; idx < 72 * 68; idx += 1024) {
                int r = idx / 68, c = idx % 68;
                int gx = tileX - 2 + c;
                float s = 0.f;
#pragma unroll
                for (int k = 0; k < 5; k++) {
                    int lx = reflect_idx(gx + k - 2, W) - (tileX - 4);
                    s += w[k] * sG[r][lx];
                }
                sH[r][c] = s;
            }
        }
    }
    __syncthreads();   // sG dead -> sV writable

    // blurV: 68 rows x 68 cols
    {
        const float w[5] = { GW2, GW1, GW0, GW1, GW2 };
        if (interior) {
            for (int idx = tid; idx < 68 * 68; idx += 1024) {
                int r = idx / 68, c = idx % 68;
                float s = 0.f;
#pragma unroll
                for (int k = 0; k < 5; k++) s += w[k] * sH[r + k][c];
                sV[r][c] = s;
            }
        } else {
            for (int idx = tid; idx < 68 * 68; idx += 1024) {
                int r = idx / 68, c = idx % 68;
                int gy = tileY - 2 + r;
                float s = 0.f;
#pragma unroll
                for (int k = 0; k < 5; k++) {
                    int ly = reflect_idx(gy + k - 2, H) - (tileY - 4);
                    s += w[k] * sH[ly][c];
                }
                sV[r][c] = s;
            }
        }
    }
    __syncthreads();   // sH dead -> sM writable

    // sobel: 66 x 66
    for (int idx = tid; idx < 66 * 66; idx += 1024) {
        int r = idx / 66, c = idx % 66;
        float a00, a01, a02, a10, a12, a20, a21, a22;
        if (interior) {
            a00 = sV[r][c];     a01 = sV[r][c + 1];     a02 = sV[r][c + 2];
            a10 = sV[r + 1][c];                         a12 = sV[r + 1][c + 2];
            a20 = sV[r + 2][c]; a21 = sV[r + 2][c + 1]; a22 = sV[r + 2][c + 2];
        } else {
            int gy = tileY - 1 + r;
            int gx = tileX - 1 + c;
            int xm = max(gx - 1, 0), xp = min(gx + 1, W - 1);
            int ym = max(gy - 1, 0), yp = min(gy + 1, H - 1);
            int xc = min(max(gx, 0), W - 1), yc = min(max(gy, 0), H - 1);
            int lxm = xm - (tileX - 2), lxp = xp - (tileX - 2), lxc = xc - (tileX - 2);
            int lym = ym - (tileY - 2), lyp = yp - (tileY - 2), lyc = yc - (tileY - 2);
            a00 = sV[lym][lxm]; a01 = sV[lym][lxc]; a02 = sV[lym][lxp];
            a10 = sV[lyc][lxm];                     a12 = sV[lyc][lxp];
            a20 = sV[lyp][lxm]; a21 = sV[lyp][lxc]; a22 = sV[lyp][lxp];
        }

        float gxv = (a02 - a00) + 2.f * (a12 - a10) + (a22 - a20);
        float gyv = (a20 - a00) + 2.f * (a21 - a01) + (a22 - a02);

        float mag = sqrtf(gxv * gxv + gyv * gyv + 1e-6f);

        float ax = fabsf(gxv), ay = fabsf(gyv);
        int d;
        if (ay <= TAN22 * ax)      d = (gxv >= 0.f) ? 0 : 4;
        else if (ay >= TAN67 * ax) d = (gyv >= 0.f) ? 2 : 6;
        else {
            if (gxv > 0.f) d = (gyv > 0.f) ? 1 : 7;
            else           d = (gyv > 0.f) ? 3 : 5;
        }
        sM[r][c] = mag;
        sD[r][c] = (unsigned char)d;
    }
    __syncthreads();

    // NMS + threshold, 4 pixels/thread
    unsigned char stv[4];
#pragma unroll
    for (int k = 0; k < 4; k++) {
        int p   = tid + 1024 * k;
        int ly2 = p >> 6, lx2 = p & 63;
        int gx  = tileX + lx2, gy = tileY + ly2;
        float m = sM[ly2 + 1][lx2 + 1];
        int d   = sD[ly2 + 1][lx2 + 1];
        int dn  = (d + 4) & 7;

        float n1, n2;
        if (interior) {
            n1 = sM[ly2 + 1 + c_dy[d]][lx2 + 1 + c_dx[d]];
            n2 = sM[ly2 + 1 + c_dy[dn]][lx2 + 1 + c_dx[dn]];
        } else {
            int y1 = gy + c_dy[d],  x1 = gx + c_dx[d];
            int y2 = gy + c_dy[dn], x2 = gx + c_dx[dn];
            n1 = (y1 >= 0 && y1 < H && x1 >= 0 && x1 < W)
                 ? sM[ly2 + 1 + c_dy[d]][lx2 + 1 + c_dx[d]] : 0.f;
            n2 = (y2 >= 0 && y2 < H && x2 >= 0 && x2 < W)
                 ? sM[ly2 + 1 + c_dy[dn]][lx2 + 1 + c_dx[dn]] : 0.f;
        }

        bool keep = (m > n1) && (m > n2);
        float mo = keep ? m : 0.f;
        magOut[(b << 20) + (gy << 10) + gx] = mo;
        stv[k] = mo > 0.2f ? 2 : (mo > 0.1f ? 1 : 0);
    }
    __syncthreads();   // sM/sD dead -> lp/ls/sflag writable

    // local CCL init
#pragma unroll
    for (int k = 0; k < 4; k++) {
        int p = tid + 1024 * k;
        ls[p] = stv[k];
        lp[p] = p;
        sflag[p] = 0;
    }
    __syncthreads();

    // reduced unions
#pragma unroll
    for (int k = 0; k < 4; k++) {
        int p = tid + 1024 * k;
        if (stv[k]) {
            int ly2 = p >> 6, lx2 = p & 63;
            bool up = (ly2 > 0) && ls[p - 64];
            bool ul = (ly2 > 0) && (lx2 > 0)  && ls[p - 65];
            bool ur = (ly2 > 0) && (lx2 < 63) && ls[p - 63];
            bool lf = (lx2 > 0) && ls[p - 1];
            if (up) lunion(lp, p, p - 64);
            else {
                if (ul) lunion(lp, p, p - 65);
                if (ur) lunion(lp, p, p - 63);
            }
            if (lf && !(up && ul)) lunion(lp, p, p - 1);
        }
    }
    __syncthreads();

    unsigned rv[4];
#pragma unroll
    for (int k = 0; k < 4; k++) {
        int p = tid + 1024 * k;
        rv[k] = 0;
        if (stv[k]) {
            rv[k] = lfind(lp, p);
            if (stv[k] == 2) sflag[rv[k]] = 1;   // only 1s written
        }
    }
    __syncthreads();

#pragma unroll
    for (int k = 0; k < 4; k++) {
        int p = tid + 1024 * k;
        int ly2 = p >> 6, lx2 = p & 63;
        unsigned gid = (b << 20) + ((tileY + ly2) << 10) + tileX + lx2;
        g_pack[gid] = stv[k] ? (unsigned short)(((unsigned)stv[k] << 12) | rv[k]) : 0;
        if (stv[k] && rv[k] == (unsigned)p) {
            g_parent[gid] = gid;
            g_flag[gid]   = sflag[p];
            unsigned slot = atomicAdd(&scnt, 1u);
            if (slot < MAXROOTS) g_roots[tileId * MAXROOTS + slot] = (unsigned short)p;
        }
    }
    __syncthreads();
    if (tid == 0) g_cnt[tileId] = min(scnt, (unsigned)MAXROOTS);
}

// ================= cross-tile border unions (well-founded reduction) ==========
#define V_PER 15360u               // 15 seams * 1024
#define V_TOT (4u * V_PER)

__global__ void k_merge_border() {
    unsigned id = blockIdx.x * blockDim.x + threadIdx.x;
    bool vert = id < V_TOT;
    unsigned t = vert ? id : id - V_TOT;
    unsigned b = t / V_PER;
    unsigned r = t % V_PER;

    if (vert) {
        unsigned seam = r >> 10;
        unsigned y = r & 1023;
        unsigned x = (seam + 1) << 6;
        unsigned i = b * IMG + y * W + x;
        unsigned pki = g_pack[i];
        if (!(pki >> 12)) return;
        unsigned ri = rootPos(i, pki);

        unsigned pkL = g_pack[i - 1];
        bool bL = (pkL >> 12) != 0;
        bool bP = false, bUL = false;
        unsigned pkUL = 0;
        if (y > 0) {
            bP   = (g_pack[i - W] >> 12) != 0;
            pkUL = g_pack[i - W - 1];
            bUL  = (pkUL >> 12) != 0;
        }
        // p~P guaranteed when bP: intra-tile (y%64!=0) or corner (horizontal
        // kernel never skips at x%64==0).
        if (bL) {
            if (!(bP && bUL)) gunion(ri, rootPos(i - 1, pkL));
        } else {
            if (bUL && !bP) gunion(ri, rootPos(i - W - 1, pkUL));
            if (y < H - 1) {
                unsigned pkDL = g_pack[i + W - 1];
                if (pkDL >> 12) gunion(ri, rootPos(i + W - 1, pkDL));
            }
        }
    } else {
        unsigned seam = r >> 10;
        unsigned x = r & 1023;
        unsigned y = (seam + 1) << 6;
        unsigned i = b * IMG + y * W + x;
        unsigned pki = g_pack[i];
        if (!(pki >> 12)) return;
        unsigned ri = rootPos(i, pki);

        unsigned pkU = g_pack[i - W];
        bool bU = (pkU >> 12) != 0;
        bool intra = (x & 63u) != 0;
        unsigned pkUL = 0;
        bool bL = false, bUL = false;
        if (x > 0) {
            bL   = (g_pack[i - 1] >> 12) != 0;
            pkUL = g_pack[i - W - 1];
            bUL  = (pkUL >> 12) != 0;
        }
        bool skip = intra && bL && bUL;   // p~L local, L~UL induction on x, UL~U upper local
        if (bU) {
            if (!skip) gunion(ri, rootPos(i - W, pkU));
        } else {
            if (bUL && !(intra && bL)) gunion(ri, rootPos(i - W - 1, pkUL));
            if (x < W - 1) {
                unsigned pkUR = g_pack[i - W + 1];
                if (pkUR >> 12) gunion(ri, rootPos(i - W + 1, pkUR));
            }
        }
    }
}

// ================= flatten roots + OR strong flag to global root =================
__global__ void k_flatten() {
    unsigned tile = blockIdx.x;
    unsigned cnt  = g_cnt[tile];
    unsigned b    = tile >> 8;
    unsigned ty   = (tile >> 4) & 15u;
    unsigned tx   = tile & 15u;
    unsigned base = (b << 20) + ((ty << 6) << 10) + (tx << 6);
    for (unsigned s = threadIdx.x; s < cnt; s += blockDim.x) {
        unsigned l = g_roots[tile * MAXROOTS + s];
        unsigned pos = base + ((l >> 6) << 10) + (l & 63u);
        unsigned rt = gfind(pos);
        g_parent[pos] = rt;
        if (rt != pos && g_flag[pos]) g_flag[rt] = 1;
    }
}

// ===== push resolved flag down to local roots (parent frozen => deterministic) =====
__global__ void k_flatten2() {
    unsigned tile = blockIdx.x;
    unsigned cnt  = g_cnt[tile];
    unsigned b    = tile >> 8;
    unsigned ty   = (tile >> 4) & 15u;
    unsigned tx   = tile & 15u;
    unsigned base = (b << 20) + ((ty << 6) << 10) + (tx << 6);
    for (unsigned s = threadIdx.x; s < cnt; s += blockDim.x) {
        unsigned l = g_roots[tile * MAXROOTS + s];
        unsigned pos = base + ((l >> 6) << 10) + (l & 63u);
        unsigned rt = __ldcg(&g_parent[pos]);
        unsigned p  = __ldcg(&g_parent[rt]);
        while (p != rt) { rt = p; p = __ldcg(&g_parent[rt]); }
        g_flagL[pos] = g_flag[rt];
    }
}

// ================= final: 2 loads per pixel, 4-way ILP =================
__global__ __launch_bounds__(256) void k_final(float* __restrict__ edgeOut) {
    const unsigned gx = blockIdx.x * 32 + threadIdx.x;
    const unsigned bz = blockIdx.z;
    const unsigned tileXb = (blockIdx.x * 32) & ~63u;
    const unsigned tileYb = (blockIdx.y * 32) & ~63u;
    const unsigned baseTile = (bz << 20) + (tileYb << 10) + tileXb;

    unsigned idx[4], pk[4];
    unsigned char fl[4];
#pragma unroll
    for (int k = 0; k < 4; k++) {
        unsigned gy = blockIdx.y * 32 + threadIdx.y + 8 * k;
        idx[k] = (bz << 20) + (gy << 10) + gx;
        pk[k]  = g_pack[idx[k]];
    }
#pragma unroll
    for (int k = 0; k < 4; k++) {
        fl[k] = 0;
        if (pk[k] >> 12) {
            unsigned l = pk[k] & 4095u;
            unsigned pos = baseTile + ((l >> 6) << 10) + (l & 63u);
            fl[k] = __ldcg(&g_flagL[pos]);
        }
    }
#pragma unroll
    for (int k = 0; k < 4; k++) {
        edgeOut[idx[k]] = fl[k] ? 1.f : 0.f;
    }
}

// ---------------- launch ----------------
extern "C" void kernel_launch(void* const* d_in, const int* in_sizes, int n_in,
                              void* d_out, int out_size) {
    const float* x = (const float*)d_in[0];
    float* magOut  = (float*)d_out;
    float* edgeOut = magOut + (size_t)NPIX;

    dim3 fblk(32, 32, 1);
    dim3 fgrd(NTX, NTY, BATCH);
    k_fused<<<fgrd, fblk>>>(x, magOut);

    unsigned nborder = 2u * V_TOT;     // 122880
    k_merge_border<<<(nborder + 255) / 256, 256>>>();

    k_flatten<<<NTILES, 256>>>();
    k_flatten2<<<NTILES, 256>>>();

    dim3 eblk(32, 8, 1);
    dim3 egrd(W / 32, H / 32, BATCH);
    k_final<<<egrd, eblk>>>(edgeOut);
}